// round 7
// baseline (speedup 1.0000x reference)
#include <cuda_runtime.h>
#include <cuda_bf16.h>
#include <math.h>

// ---------------- problem constants ----------------
#define S_LEN   8192
#define L_CHARS 16
#define CHAR_DIM 64
#define WORD_DIM 256
#define CHAR_HID 128
#define WORD_HID 512
#define N_TAG   64
#define CK      192              // CHAR_DIM + CHAR_HID (char gemm K)
#define WK      384              // WORD_DIM + CHAR_HID (word input gemm K)
#define GW      128              // persistent CTAs for word LSTM (<=148 SMs)
#define SENT    0x7fbadbadu     // NaN-pattern sentinel (h can never be NaN)

// ---------------- device scratch (no cudaMalloc allowed) ----------------
__device__ __align__(16) float g_A[S_LEN * CK];        // char gemm input [ce_t | h]
__device__ __align__(16) float g_gates[S_LEN * 512];   // char gates
__device__ __align__(16) float g_c[S_LEN * CHAR_HID];  // char cell state
__device__ __align__(16) float g_cf[S_LEN * CHAR_HID]; // char features
__device__ __align__(16) float g_Wc[512 * CK];         // concat [c_Wih | c_Whh]
__device__ __align__(16) float g_bc[512];              // c_bih + c_bhh
__device__ __align__(16) float g_bw[2048];             // w_bih + w_bhh
__device__ __align__(16) float g_F[S_LEN * WK];        // word feats [we | cf]
__device__ __align__(16) float g_wg[S_LEN * 2048];     // word input gates (unit f4)
__device__ __align__(16) float g_h[(S_LEN + 1) * 512]; // h history (row0=0, rest=SENT)

__device__ __forceinline__ float sigmoidf_(float x) { return 1.f / (1.f + expf(-x)); }

// Accurate fast activations (2-ulp MUFU exp + fast divide).
// tanh.approx.f32 (5e-4 abs err) amplifies ~600x through the 8192-step
// recurrence -> 0.316 rel_err (R4). These stay at ~1e-7 per step.
__device__ __forceinline__ float sig_acc(float x) {
    x = fminf(fmaxf(x, -30.f), 30.f);
    float e = __expf(-x);
    return __fdividef(1.f, 1.f + e);
}
__device__ __forceinline__ float tanh_acc(float x) {
    x = fminf(fmaxf(x, -15.f), 15.f);
    float e = __expf(2.f * x);
    return __fdividef(e - 1.f, e + 1.f);
}
__device__ __forceinline__ float4 ldcg_f4(const float* p) {
    float4 v;
    asm volatile("ld.global.cg.v4.f32 {%0,%1,%2,%3}, [%4];"
                 : "=f"(v.x), "=f"(v.y), "=f"(v.z), "=f"(v.w) : "l"(p) : "memory");
    return v;
}
// VOLATILE poll load: honored by nvcc AND ptxas (weak ld.cg in a spin loop is
// legally hoistable by ptxas -- that is what broke R6). Integer regs so no
// float compare can ever be generated for the NaN sentinel.
__device__ __forceinline__ uint4 ldvol_u4(const float* p) {
    uint4 v;
    asm volatile("ld.volatile.global.v4.b32 {%0,%1,%2,%3}, [%4];"
                 : "=r"(v.x), "=r"(v.y), "=r"(v.z), "=r"(v.w) : "l"(p) : "memory");
    return v;
}
__device__ __forceinline__ unsigned any_sent_u(uint4 v) {
    return (unsigned)(v.x == SENT) | (unsigned)(v.y == SENT) |
           (unsigned)(v.z == SENT) | (unsigned)(v.w == SENT);
}

// ---------------- prep: concat weights, biases, init buffers ----------------
__global__ void prep_kernel(const int* __restrict__ chars,
                            const float* __restrict__ char_embed,
                            const float* __restrict__ c_Wih,
                            const float* __restrict__ c_Whh,
                            const float* __restrict__ c_bih,
                            const float* __restrict__ c_bhh,
                            const float* __restrict__ w_bih,
                            const float* __restrict__ w_bhh) {
    int tid = blockIdx.x * blockDim.x + threadIdx.x;
    int stride = gridDim.x * blockDim.x;
    for (int i = tid; i < 512 * CK; i += stride) {
        int j = i / CK, k = i - j * CK;
        g_Wc[i] = (k < CHAR_DIM) ? c_Wih[j * CHAR_DIM + k]
                                 : c_Whh[j * CHAR_HID + (k - CHAR_DIM)];
    }
    for (int i = tid; i < 512; i += stride) g_bc[i] = c_bih[i] + c_bhh[i];
    for (int i = tid; i < 2048; i += stride) g_bw[i] = w_bih[i] + w_bhh[i];
    for (int i = tid; i < S_LEN * CHAR_HID; i += stride) g_c[i] = 0.f;
    // h history: row 0 = zeros (initial state), rows 1..S = sentinel
    for (int i = tid; i < (S_LEN + 1) * 512; i += stride) {
        unsigned bits = (i < 512) ? 0u : SENT;
        ((unsigned*)g_h)[i] = bits;
    }
    // char gemm input for t=0: ce in cols [0,64), zeros (h0) in [64,192)
    for (int i = tid; i < S_LEN * CK; i += stride) {
        int b = i / CK, k = i - b * CK;
        g_A[i] = (k < CHAR_DIM)
                   ? char_embed[chars[b * L_CHARS + 0] * CHAR_DIM + k]
                   : 0.f;
    }
}

// ---------------- generic fp32 GEMM: C = A(MxK) * B(NxK)^T + bias ----------------
// BM=128 BN=64 BK=16, 256 threads, 8x4 per-thread tile.
// mode 0: C[row*ldc+col] = acc + bias[col]
// mode 1: word-gate unit-blocked store: dst = (col&511)*4 + (col>>9)
__global__ void __launch_bounds__(256) gemm_bias(const float* __restrict__ A,
                                                 const float* __restrict__ B,
                                                 const float* __restrict__ bias,
                                                 float* __restrict__ C,
                                                 int K, int ldc, int mode) {
    __shared__ float sA[2][16][129];
    __shared__ float sB[2][16][65];
    const int bm = blockIdx.x << 7;
    const int bn = blockIdx.y << 6;
    const int tid = threadIdx.x;
    const int tx = tid & 15;
    const int ty = tid >> 4;
    const int lrow = tid >> 2;
    const int kq = (tid & 3) << 2;

    const float* Aptr = A + (size_t)(bm + lrow) * K + kq;
    const float* Bptr = B + (size_t)(bn + lrow) * K + kq;

    float acc[8][4];
#pragma unroll
    for (int i = 0; i < 8; i++)
#pragma unroll
        for (int j = 0; j < 4; j++) acc[i][j] = 0.f;

    {
        float4 v0 = *(const float4*)(Aptr);
        float4 v1 = *(const float4*)(Aptr + (size_t)64 * K);
        float4 vb = *(const float4*)(Bptr);
        sA[0][kq + 0][lrow] = v0.x; sA[0][kq + 1][lrow] = v0.y;
        sA[0][kq + 2][lrow] = v0.z; sA[0][kq + 3][lrow] = v0.w;
        sA[0][kq + 0][lrow + 64] = v1.x; sA[0][kq + 1][lrow + 64] = v1.y;
        sA[0][kq + 2][lrow + 64] = v1.z; sA[0][kq + 3][lrow + 64] = v1.w;
        sB[0][kq + 0][lrow] = vb.x; sB[0][kq + 1][lrow] = vb.y;
        sB[0][kq + 2][lrow] = vb.z; sB[0][kq + 3][lrow] = vb.w;
    }
    __syncthreads();

    const int nk = K >> 4;
    for (int kt = 0; kt < nk; kt++) {
        const int cur = kt & 1;
        float4 v0, v1, vb;
        const bool pf = (kt + 1) < nk;
        if (pf) {
            const float* Ap = Aptr + ((kt + 1) << 4);
            v0 = *(const float4*)(Ap);
            v1 = *(const float4*)(Ap + (size_t)64 * K);
            vb = *(const float4*)(Bptr + ((kt + 1) << 4));
        }
#pragma unroll
        for (int kk = 0; kk < 16; kk++) {
            float a[8], b[4];
#pragma unroll
            for (int i = 0; i < 8; i++) a[i] = sA[cur][kk][ty + 16 * i];
#pragma unroll
            for (int j = 0; j < 4; j++) b[j] = sB[cur][kk][tx + 16 * j];
#pragma unroll
            for (int i = 0; i < 8; i++)
#pragma unroll
                for (int j = 0; j < 4; j++)
                    acc[i][j] = fmaf(a[i], b[j], acc[i][j]);
        }
        if (pf) {
            const int nb = cur ^ 1;
            sA[nb][kq + 0][lrow] = v0.x; sA[nb][kq + 1][lrow] = v0.y;
            sA[nb][kq + 2][lrow] = v0.z; sA[nb][kq + 3][lrow] = v0.w;
            sA[nb][kq + 0][lrow + 64] = v1.x; sA[nb][kq + 1][lrow + 64] = v1.y;
            sA[nb][kq + 2][lrow + 64] = v1.z; sA[nb][kq + 3][lrow + 64] = v1.w;
            sB[nb][kq + 0][lrow] = vb.x; sB[nb][kq + 1][lrow] = vb.y;
            sB[nb][kq + 2][lrow] = vb.z; sB[nb][kq + 3][lrow] = vb.w;
        }
        __syncthreads();
    }

    if (mode == 0) {
#pragma unroll
        for (int i = 0; i < 8; i++) {
            int row = bm + ty + 16 * i;
#pragma unroll
            for (int j = 0; j < 4; j++) {
                int col = bn + tx + 16 * j;
                C[(size_t)row * ldc + col] = acc[i][j] + bias[col];
            }
        }
    } else {
        // unit-blocked: memory [u*4 + gt] per row, u = col&511, gt = col>>9
#pragma unroll
        for (int i = 0; i < 8; i++) {
            int row = bm + ty + 16 * i;
#pragma unroll
            for (int j = 0; j < 4; j++) {
                int col = bn + tx + 16 * j;
                int dst = (col & 511) * 4 + (col >> 9);
                C[(size_t)row * 2048 + dst] = acc[i][j] + bias[col];
            }
        }
    }
}

// ---------------- char LSTM pointwise update ----------------
__global__ void char_pointwise(const int* __restrict__ chars,
                               const int* __restrict__ char_lens,
                               const float* __restrict__ char_embed, int t) {
    int idx = blockIdx.x * blockDim.x + threadIdx.x;
    if (idx < S_LEN * CHAR_HID) {
        int b = idx >> 7, j = idx & 127;
        const float* gr = g_gates + b * 512;
        float i_ = sigmoidf_(gr[j]);
        float f_ = sigmoidf_(gr[128 + j]);
        float gg = tanhf(gr[256 + j]);
        float o_ = sigmoidf_(gr[384 + j]);
        float c = f_ * g_c[idx] + i_ * gg;
        g_c[idx] = c;
        float h = o_ * tanhf(c);
        g_A[b * CK + CHAR_DIM + j] = h;               // input for next step
        if (char_lens[b] - 1 == t) g_cf[idx] = h;     // final char feature
    }
    if (t + 1 < L_CHARS && idx < S_LEN * CHAR_DIM) {
        int b = idx >> 6, k = idx & 63;
        g_A[b * CK + k] = char_embed[chars[b * L_CHARS + (t + 1)] * CHAR_DIM + k];
    }
}

// ---------------- word feature gather ----------------
__global__ void feats_kernel(const int* __restrict__ x,
                             const float* __restrict__ word_embed) {
    int i = blockIdx.x * blockDim.x + threadIdx.x;
    if (i < S_LEN * WK) {
        int s = i / WK, k = i - s * WK;
        g_F[i] = (k < WORD_DIM) ? word_embed[x[s] * WORD_DIM + k]
                                : g_cf[s * CHAR_HID + (k - WORD_DIM)];
    }
}

// ---------------- persistent word LSTM recurrence ----------------
// GW=128 CTAs x 128 threads, warp <-> hidden unit (512 warps = 512 units).
// Lane l holds all 4 gate rows of its unit over h-cols [l*16, l*16+16)
// (64 weight floats register-resident). SENTINEL DATAFLOW: h rows are
// pre-poisoned; consumers poll the h data itself with ld.VOLATILE (strong
// enough that ptxas cannot hoist the spin loads -- the R6 failure mode).
// No flags, no fences, no __syncthreads; warps free-run as a systolic
// pipeline coupled only through the data (4B store atomicity; h never NaN).
__global__ void __launch_bounds__(128) word_lstm_kernel(const float* __restrict__ Whh) {
    const int cta = blockIdx.x;
    const int tid = threadIdx.x;
    const int w = tid >> 5;               // local unit 0..3
    const int lane = tid & 31;
    const int u = cta * 4 + w;            // global hidden unit 0..511

    // register-resident W_hh: rows {gt*512+u}, cols [lane*16, lane*16+16)
    float4 wv[4][4];
#pragma unroll
    for (int gt = 0; gt < 4; gt++) {
        const float4* p = (const float4*)(Whh + (size_t)(gt * 512 + u) * 512 + lane * 16);
#pragma unroll
        for (int q = 0; q < 4; q++) wv[gt][q] = p[q];
    }

    const bool l0 = (lane == 0);
    float c = 0.f;
    float4 wg_cur = make_float4(0.f, 0.f, 0.f, 0.f);
    float4 wg_nxt = wg_cur;
    if (l0) {
        wg_cur = *(const float4*)(g_wg + (size_t)0 * 2048 + u * 4);
        wg_nxt = *(const float4*)(g_wg + (size_t)1 * 2048 + u * 4);
    }

    const float* hb0 = g_h + lane * 16;

    for (int s = 0; s < S_LEN; s++) {
        // prefetch input gates two steps ahead (DRAM stream, hidden by poll)
        float4 wg_pf = make_float4(0.f, 0.f, 0.f, 0.f);
        if (l0 && s + 2 < S_LEN)
            wg_pf = ldcg_f4(g_wg + (size_t)(s + 2) * 2048 + u * 4);

        // poll this lane's 16-float h slice until fully published
        const float* hb = hb0 + (size_t)s * 512;
        uint4 u0, u1, u2, u3;
        do {
            u0 = ldvol_u4(hb + 0);
            u1 = ldvol_u4(hb + 4);
            u2 = ldvol_u4(hb + 8);
            u3 = ldvol_u4(hb + 12);
        } while (any_sent_u(u0) | any_sent_u(u1) | any_sent_u(u2) | any_sent_u(u3));

        float4 h0 = make_float4(__uint_as_float(u0.x), __uint_as_float(u0.y),
                                __uint_as_float(u0.z), __uint_as_float(u0.w));
        float4 h1 = make_float4(__uint_as_float(u1.x), __uint_as_float(u1.y),
                                __uint_as_float(u1.z), __uint_as_float(u1.w));
        float4 h2 = make_float4(__uint_as_float(u2.x), __uint_as_float(u2.y),
                                __uint_as_float(u2.z), __uint_as_float(u2.w));
        float4 h3 = make_float4(__uint_as_float(u3.x), __uint_as_float(u3.y),
                                __uint_as_float(u3.z), __uint_as_float(u3.w));

        float a0 = 0.f, a1 = 0.f, a2 = 0.f, a3 = 0.f;
#pragma unroll
        for (int gt = 0; gt < 4; gt++) {
            float acc = 0.f;
            acc = fmaf(wv[gt][0].x, h0.x, acc); acc = fmaf(wv[gt][0].y, h0.y, acc);
            acc = fmaf(wv[gt][0].z, h0.z, acc); acc = fmaf(wv[gt][0].w, h0.w, acc);
            acc = fmaf(wv[gt][1].x, h1.x, acc); acc = fmaf(wv[gt][1].y, h1.y, acc);
            acc = fmaf(wv[gt][1].z, h1.z, acc); acc = fmaf(wv[gt][1].w, h1.w, acc);
            acc = fmaf(wv[gt][2].x, h2.x, acc); acc = fmaf(wv[gt][2].y, h2.y, acc);
            acc = fmaf(wv[gt][2].z, h2.z, acc); acc = fmaf(wv[gt][2].w, h2.w, acc);
            acc = fmaf(wv[gt][3].x, h3.x, acc); acc = fmaf(wv[gt][3].y, h3.y, acc);
            acc = fmaf(wv[gt][3].z, h3.z, acc); acc = fmaf(wv[gt][3].w, h3.w, acc);
            if (gt == 0) a0 = acc; else if (gt == 1) a1 = acc;
            else if (gt == 2) a2 = acc; else a3 = acc;
        }

        // full-warp butterfly reduce (4 values); also reconverges the warp
#pragma unroll
        for (int off = 16; off > 0; off >>= 1) {
            a0 += __shfl_xor_sync(0xffffffffu, a0, off);
            a1 += __shfl_xor_sync(0xffffffffu, a1, off);
            a2 += __shfl_xor_sync(0xffffffffu, a2, off);
            a3 += __shfl_xor_sync(0xffffffffu, a3, off);
        }

        if (l0) {
            float i_ = sig_acc(a0 + wg_cur.x);
            float f_ = sig_acc(a1 + wg_cur.y);
            float g_ = tanh_acc(a2 + wg_cur.z);
            float o_ = sig_acc(a3 + wg_cur.w);
            c = f_ * c + i_ * g_;
            float h = o_ * tanh_acc(c);   // bounded: never NaN == sentinel-safe
            asm volatile("st.volatile.global.b32 [%0], %1;"
                         :: "l"(g_h + (size_t)(s + 1) * 512 + u),
                            "r"(__float_as_uint(h)) : "memory");
            wg_cur = wg_nxt;
            wg_nxt = wg_pf;
        }
    }
}

// ---------------- host launch ----------------
extern "C" void kernel_launch(void* const* d_in, const int* in_sizes, int n_in,
                              void* d_out, int out_size) {
    (void)in_sizes; (void)n_in; (void)out_size;
    const int*   x          = (const int*)d_in[0];
    const int*   chars      = (const int*)d_in[1];
    const int*   char_lens  = (const int*)d_in[2];
    const float* word_embed = (const float*)d_in[3];
    const float* char_embed = (const float*)d_in[4];
    const float* c_Wih      = (const float*)d_in[5];
    const float* c_Whh      = (const float*)d_in[6];
    const float* c_bih      = (const float*)d_in[7];
    const float* c_bhh      = (const float*)d_in[8];
    const float* w_Wih      = (const float*)d_in[9];
    const float* w_Whh      = (const float*)d_in[10];
    const float* w_bih      = (const float*)d_in[11];
    const float* w_bhh      = (const float*)d_in[12];
    const float* cls_W      = (const float*)d_in[13];
    const float* cls_b      = (const float*)d_in[14];
    float* out = (float*)d_out;

    float *pA, *pWc, *pbc, *pgates, *pbw, *pF, *pwg, *ph;
    cudaGetSymbolAddress((void**)&pA,     g_A);
    cudaGetSymbolAddress((void**)&pWc,    g_Wc);
    cudaGetSymbolAddress((void**)&pbc,    g_bc);
    cudaGetSymbolAddress((void**)&pgates, g_gates);
    cudaGetSymbolAddress((void**)&pbw,    g_bw);
    cudaGetSymbolAddress((void**)&pF,     g_F);
    cudaGetSymbolAddress((void**)&pwg,    g_wg);
    cudaGetSymbolAddress((void**)&ph,     g_h);

    prep_kernel<<<1024, 256>>>(chars, char_embed, c_Wih, c_Whh,
                               c_bih, c_bhh, w_bih, w_bhh);

    // char LSTM: 16 x (gates GEMM + pointwise)
    for (int t = 0; t < L_CHARS; t++) {
        gemm_bias<<<dim3(S_LEN / 128, 512 / 64), 256>>>(
            pA, pWc, pbc, pgates, CK, 512, 0);
        char_pointwise<<<(S_LEN * CHAR_HID) / 256, 256>>>(
            chars, char_lens, char_embed, t);
    }

    // word features + input-gate precompute (unit-blocked, biases folded)
    feats_kernel<<<(S_LEN * WK + 255) / 256, 256>>>(x, word_embed);
    gemm_bias<<<dim3(S_LEN / 128, 2048 / 64), 256>>>(
        pF, w_Wih, pbw, pwg, WK, 2048, 1);

    // sequential word LSTM (persistent, volatile sentinel dataflow)
    word_lstm_kernel<<<GW, 128>>>(w_Whh);

    // classifier: out = h_all @ cls_W^T + cls_b  (A offset by one row: h[1..S])
    gemm_bias<<<dim3(S_LEN / 128, 1), 256>>>(
        ph + 512, cls_W, cls_b, out, 512, N_TAG, 0);
}

// round 8
// speedup vs baseline: 6.3589x; 6.3589x over previous
#include <cuda_runtime.h>
#include <cuda_bf16.h>
#include <math.h>

// ---------------- problem constants ----------------
#define S_LEN   8192
#define L_CHARS 16
#define CHAR_DIM 64
#define WORD_DIM 256
#define CHAR_HID 128
#define WORD_HID 512
#define N_TAG   64
#define CK      192              // CHAR_DIM + CHAR_HID (char gemm K)
#define WK      384              // WORD_DIM + CHAR_HID (word input gemm K)
#define GW2     64               // persistent CTAs for word LSTM
#define TPB2    256              // threads per word-LSTM CTA (8 warps = 8 units)

// ---------------- device scratch (no cudaMalloc allowed) ----------------
__device__ __align__(16) float g_A[S_LEN * CK];        // char gemm input [ce_t | h]
__device__ __align__(16) float g_gates[S_LEN * 512];   // char gates
__device__ __align__(16) float g_c[S_LEN * CHAR_HID];  // char cell state
__device__ __align__(16) float g_cf[S_LEN * CHAR_HID]; // char features
__device__ __align__(16) float g_Wc[512 * CK];         // concat [c_Wih | c_Whh]
__device__ __align__(16) float g_bc[512];              // c_bih + c_bhh
__device__ __align__(16) float g_bw[2048];             // w_bih + w_bhh
__device__ __align__(16) float g_F[S_LEN * WK];        // word feats [we | cf]
__device__ __align__(16) float g_wg[S_LEN * 2048];     // word input gates (unit f4)
__device__ __align__(16) float g_h[(S_LEN + 1) * 512]; // h history (row0 = 0)
__device__ int g_flag[GW2 * 32];                       // flags, 128B apart (1 line each)

__device__ __forceinline__ float sigmoidf_(float x) { return 1.f / (1.f + expf(-x)); }

// Accurate fast activations (2-ulp MUFU exp + fast divide).
// tanh.approx.f32 (5e-4 abs err) amplifies ~600x through the 8192-step
// recurrence -> 0.316 rel_err (R4). These stay at ~1e-7 per step.
__device__ __forceinline__ float sig_acc(float x) {
    x = fminf(fmaxf(x, -30.f), 30.f);
    float e = __expf(-x);
    return __fdividef(1.f, 1.f + e);
}
__device__ __forceinline__ float tanh_acc(float x) {
    x = fminf(fmaxf(x, -15.f), 15.f);
    float e = __expf(2.f * x);
    return __fdividef(e - 1.f, e + 1.f);
}
__device__ __forceinline__ float4 ldcg_f4(const float* p) {
    float4 v;
    asm volatile("ld.global.cg.v4.f32 {%0,%1,%2,%3}, [%4];"
                 : "=f"(v.x), "=f"(v.y), "=f"(v.z), "=f"(v.w) : "l"(p) : "memory");
    return v;
}

// ---------------- prep: concat weights, biases, init buffers ----------------
__global__ void prep_kernel(const int* __restrict__ chars,
                            const float* __restrict__ char_embed,
                            const float* __restrict__ c_Wih,
                            const float* __restrict__ c_Whh,
                            const float* __restrict__ c_bih,
                            const float* __restrict__ c_bhh,
                            const float* __restrict__ w_bih,
                            const float* __restrict__ w_bhh) {
    int tid = blockIdx.x * blockDim.x + threadIdx.x;
    int stride = gridDim.x * blockDim.x;
    for (int i = tid; i < 512 * CK; i += stride) {
        int j = i / CK, k = i - j * CK;
        g_Wc[i] = (k < CHAR_DIM) ? c_Wih[j * CHAR_DIM + k]
                                 : c_Whh[j * CHAR_HID + (k - CHAR_DIM)];
    }
    for (int i = tid; i < 512; i += stride) g_bc[i] = c_bih[i] + c_bhh[i];
    for (int i = tid; i < 2048; i += stride) g_bw[i] = w_bih[i] + w_bhh[i];
    for (int i = tid; i < S_LEN * CHAR_HID; i += stride) g_c[i] = 0.f;
    for (int i = tid; i < 512; i += stride) g_h[i] = 0.f;   // initial hidden state
    for (int i = tid; i < GW2 * 32; i += stride) g_flag[i] = 0;  // reset per launch
    // char gemm input for t=0: ce in cols [0,64), zeros (h0) in [64,192)
    for (int i = tid; i < S_LEN * CK; i += stride) {
        int b = i / CK, k = i - b * CK;
        g_A[i] = (k < CHAR_DIM)
                   ? char_embed[chars[b * L_CHARS + 0] * CHAR_DIM + k]
                   : 0.f;
    }
}

// ---------------- generic fp32 GEMM: C = A(MxK) * B(NxK)^T + bias ----------------
// BM=128 BN=64 BK=16, 256 threads, 8x4 per-thread tile.
// mode 0: C[row*ldc+col] = acc + bias[col]
// mode 1: word-gate unit-blocked store: dst = (col&511)*4 + (col>>9)
__global__ void __launch_bounds__(256) gemm_bias(const float* __restrict__ A,
                                                 const float* __restrict__ B,
                                                 const float* __restrict__ bias,
                                                 float* __restrict__ C,
                                                 int K, int ldc, int mode) {
    __shared__ float sA[2][16][129];
    __shared__ float sB[2][16][65];
    const int bm = blockIdx.x << 7;
    const int bn = blockIdx.y << 6;
    const int tid = threadIdx.x;
    const int tx = tid & 15;
    const int ty = tid >> 4;
    const int lrow = tid >> 2;
    const int kq = (tid & 3) << 2;

    const float* Aptr = A + (size_t)(bm + lrow) * K + kq;
    const float* Bptr = B + (size_t)(bn + lrow) * K + kq;

    float acc[8][4];
#pragma unroll
    for (int i = 0; i < 8; i++)
#pragma unroll
        for (int j = 0; j < 4; j++) acc[i][j] = 0.f;

    {
        float4 v0 = *(const float4*)(Aptr);
        float4 v1 = *(const float4*)(Aptr + (size_t)64 * K);
        float4 vb = *(const float4*)(Bptr);
        sA[0][kq + 0][lrow] = v0.x; sA[0][kq + 1][lrow] = v0.y;
        sA[0][kq + 2][lrow] = v0.z; sA[0][kq + 3][lrow] = v0.w;
        sA[0][kq + 0][lrow + 64] = v1.x; sA[0][kq + 1][lrow + 64] = v1.y;
        sA[0][kq + 2][lrow + 64] = v1.z; sA[0][kq + 3][lrow + 64] = v1.w;
        sB[0][kq + 0][lrow] = vb.x; sB[0][kq + 1][lrow] = vb.y;
        sB[0][kq + 2][lrow] = vb.z; sB[0][kq + 3][lrow] = vb.w;
    }
    __syncthreads();

    const int nk = K >> 4;
    for (int kt = 0; kt < nk; kt++) {
        const int cur = kt & 1;
        float4 v0, v1, vb;
        const bool pf = (kt + 1) < nk;
        if (pf) {
            const float* Ap = Aptr + ((kt + 1) << 4);
            v0 = *(const float4*)(Ap);
            v1 = *(const float4*)(Ap + (size_t)64 * K);
            vb = *(const float4*)(Bptr + ((kt + 1) << 4));
        }
#pragma unroll
        for (int kk = 0; kk < 16; kk++) {
            float a[8], b[4];
#pragma unroll
            for (int i = 0; i < 8; i++) a[i] = sA[cur][kk][ty + 16 * i];
#pragma unroll
            for (int j = 0; j < 4; j++) b[j] = sB[cur][kk][tx + 16 * j];
#pragma unroll
            for (int i = 0; i < 8; i++)
#pragma unroll
                for (int j = 0; j < 4; j++)
                    acc[i][j] = fmaf(a[i], b[j], acc[i][j]);
        }
        if (pf) {
            const int nb = cur ^ 1;
            sA[nb][kq + 0][lrow] = v0.x; sA[nb][kq + 1][lrow] = v0.y;
            sA[nb][kq + 2][lrow] = v0.z; sA[nb][kq + 3][lrow] = v0.w;
            sA[nb][kq + 0][lrow + 64] = v1.x; sA[nb][kq + 1][lrow + 64] = v1.y;
            sA[nb][kq + 2][lrow + 64] = v1.z; sA[nb][kq + 3][lrow + 64] = v1.w;
            sB[nb][kq + 0][lrow] = vb.x; sB[nb][kq + 1][lrow] = vb.y;
            sB[nb][kq + 2][lrow] = vb.z; sB[nb][kq + 3][lrow] = vb.w;
        }
        __syncthreads();
    }

    if (mode == 0) {
#pragma unroll
        for (int i = 0; i < 8; i++) {
            int row = bm + ty + 16 * i;
#pragma unroll
            for (int j = 0; j < 4; j++) {
                int col = bn + tx + 16 * j;
                C[(size_t)row * ldc + col] = acc[i][j] + bias[col];
            }
        }
    } else {
        // unit-blocked: memory [u*4 + gt] per row, u = col&511, gt = col>>9
#pragma unroll
        for (int i = 0; i < 8; i++) {
            int row = bm + ty + 16 * i;
#pragma unroll
            for (int j = 0; j < 4; j++) {
                int col = bn + tx + 16 * j;
                int dst = (col & 511) * 4 + (col >> 9);
                C[(size_t)row * 2048 + dst] = acc[i][j] + bias[col];
            }
        }
    }
}

// ---------------- char LSTM pointwise update ----------------
__global__ void char_pointwise(const int* __restrict__ chars,
                               const int* __restrict__ char_lens,
                               const float* __restrict__ char_embed, int t) {
    int idx = blockIdx.x * blockDim.x + threadIdx.x;
    if (idx < S_LEN * CHAR_HID) {
        int b = idx >> 7, j = idx & 127;
        const float* gr = g_gates + b * 512;
        float i_ = sigmoidf_(gr[j]);
        float f_ = sigmoidf_(gr[128 + j]);
        float gg = tanhf(gr[256 + j]);
        float o_ = sigmoidf_(gr[384 + j]);
        float c = f_ * g_c[idx] + i_ * gg;
        g_c[idx] = c;
        float h = o_ * tanhf(c);
        g_A[b * CK + CHAR_DIM + j] = h;               // input for next step
        if (char_lens[b] - 1 == t) g_cf[idx] = h;     // final char feature
    }
    if (t + 1 < L_CHARS && idx < S_LEN * CHAR_DIM) {
        int b = idx >> 6, k = idx & 63;
        g_A[b * CK + k] = char_embed[chars[b * L_CHARS + (t + 1)] * CHAR_DIM + k];
    }
}

// ---------------- word feature gather ----------------
__global__ void feats_kernel(const int* __restrict__ x,
                             const float* __restrict__ word_embed) {
    int i = blockIdx.x * blockDim.x + threadIdx.x;
    if (i < S_LEN * WK) {
        int s = i / WK, k = i - s * WK;
        g_F[i] = (k < WORD_DIM) ? word_embed[x[s] * WORD_DIM + k]
                                : g_cf[s * CHAR_HID + (k - WORD_DIM)];
    }
}

// ---------------- persistent word LSTM recurrence ----------------
// GW2=64 CTAs x 256 threads, warp <-> hidden unit (512 warps = 512 units).
// Lane l holds all 4 gate rows of its unit over h-cols [l*16, l*16+16)
// (64 weight floats register-resident). Sync: hierarchical flag wait --
// only 64 threads/CTA poll (one flag each, flags on DISTINCT 128B lines,
// scalar ld.volatile) -> 4096 pollers x 4B ~ 500B/cy chip-wide, no LTS
// hotspot (R5: 16k pollers on 4 lines; R7: 16k x 64B volatile = LTS
// saturation). Everyone else waits at the CTA bar. h itself is read once
// per step with plain ld.cg after the bar (ordered by poll + bar).
__global__ void __launch_bounds__(TPB2) word_lstm_kernel(const float* __restrict__ Whh) {
    const int cta = blockIdx.x;
    const int tid = threadIdx.x;
    const int w = tid >> 5;               // local unit 0..7
    const int lane = tid & 31;
    const int u = cta * 8 + w;            // global hidden unit 0..511

    // register-resident W_hh: rows {gt*512+u}, cols [lane*16, lane*16+16)
    float4 wv[4][4];
#pragma unroll
    for (int gt = 0; gt < 4; gt++) {
        const float4* p = (const float4*)(Whh + (size_t)(gt * 512 + u) * 512 + lane * 16);
#pragma unroll
        for (int q = 0; q < 4; q++) wv[gt][q] = p[q];
    }

    const bool l0 = (lane == 0);
    float c = 0.f;
    float4 wg_cur = make_float4(0.f, 0.f, 0.f, 0.f);
    float4 wg_nxt = wg_cur;
    if (l0) {
        wg_cur = *(const float4*)(g_wg + (size_t)0 * 2048 + u * 4);
        wg_nxt = *(const float4*)(g_wg + (size_t)1 * 2048 + u * 4);
    }

    const int* myflag = g_flag + tid * 32;   // only used when tid < GW2

    for (int s = 0; s < S_LEN; s++) {
        // prefetch input gates two steps ahead (DRAM stream, hidden by wait)
        float4 wg_pf = make_float4(0.f, 0.f, 0.f, 0.f);
        if (l0 && s + 2 < S_LEN)
            wg_pf = ldcg_f4(g_wg + (size_t)(s + 2) * 2048 + u * 4);

        // wait until every producer CTA has published h[s]
        if (s > 0) {
            if (tid < GW2) {
                int v;
                do {
                    asm volatile("ld.volatile.global.u32 %0, [%1];"
                                 : "=r"(v) : "l"(myflag) : "memory");
                } while (v < s);
            }
            __syncthreads();
        }

        // h slice (16 floats, L2-coherent, read once)
        const float* hb = g_h + (size_t)s * 512 + lane * 16;
        float4 h0 = ldcg_f4(hb + 0);
        float4 h1 = ldcg_f4(hb + 4);
        float4 h2 = ldcg_f4(hb + 8);
        float4 h3 = ldcg_f4(hb + 12);

        float a0 = 0.f, a1 = 0.f, a2 = 0.f, a3 = 0.f;
#pragma unroll
        for (int gt = 0; gt < 4; gt++) {
            float acc = 0.f;
            acc = fmaf(wv[gt][0].x, h0.x, acc); acc = fmaf(wv[gt][0].y, h0.y, acc);
            acc = fmaf(wv[gt][0].z, h0.z, acc); acc = fmaf(wv[gt][0].w, h0.w, acc);
            acc = fmaf(wv[gt][1].x, h1.x, acc); acc = fmaf(wv[gt][1].y, h1.y, acc);
            acc = fmaf(wv[gt][1].z, h1.z, acc); acc = fmaf(wv[gt][1].w, h1.w, acc);
            acc = fmaf(wv[gt][2].x, h2.x, acc); acc = fmaf(wv[gt][2].y, h2.y, acc);
            acc = fmaf(wv[gt][2].z, h2.z, acc); acc = fmaf(wv[gt][2].w, h2.w, acc);
            acc = fmaf(wv[gt][3].x, h3.x, acc); acc = fmaf(wv[gt][3].y, h3.y, acc);
            acc = fmaf(wv[gt][3].z, h3.z, acc); acc = fmaf(wv[gt][3].w, h3.w, acc);
            if (gt == 0) a0 = acc; else if (gt == 1) a1 = acc;
            else if (gt == 2) a2 = acc; else a3 = acc;
        }

        // full-warp butterfly reduce (4 values)
#pragma unroll
        for (int off = 16; off > 0; off >>= 1) {
            a0 += __shfl_xor_sync(0xffffffffu, a0, off);
            a1 += __shfl_xor_sync(0xffffffffu, a1, off);
            a2 += __shfl_xor_sync(0xffffffffu, a2, off);
            a3 += __shfl_xor_sync(0xffffffffu, a3, off);
        }

        if (l0) {
            float i_ = sig_acc(a0 + wg_cur.x);
            float f_ = sig_acc(a1 + wg_cur.y);
            float g_ = tanh_acc(a2 + wg_cur.z);
            float o_ = sig_acc(a3 + wg_cur.w);
            c = f_ * c + i_ * g_;
            float h = o_ * tanh_acc(c);
            asm volatile("st.global.cg.f32 [%0], %1;"
                         :: "l"(g_h + (size_t)(s + 1) * 512 + u), "f"(h) : "memory");
            wg_cur = wg_nxt;
            wg_nxt = wg_pf;
        }
        // publish: bar (drains the 8 unit stores) -> gpu fence -> flag
        __syncthreads();
        if (tid == 0) {
            __threadfence();
            asm volatile("st.volatile.global.u32 [%0], %1;"
                         :: "l"(g_flag + cta * 32), "r"(s + 1) : "memory");
        }
    }
}

// ---------------- host launch ----------------
extern "C" void kernel_launch(void* const* d_in, const int* in_sizes, int n_in,
                              void* d_out, int out_size) {
    (void)in_sizes; (void)n_in; (void)out_size;
    const int*   x          = (const int*)d_in[0];
    const int*   chars      = (const int*)d_in[1];
    const int*   char_lens  = (const int*)d_in[2];
    const float* word_embed = (const float*)d_in[3];
    const float* char_embed = (const float*)d_in[4];
    const float* c_Wih      = (const float*)d_in[5];
    const float* c_Whh      = (const float*)d_in[6];
    const float* c_bih      = (const float*)d_in[7];
    const float* c_bhh      = (const float*)d_in[8];
    const float* w_Wih      = (const float*)d_in[9];
    const float* w_Whh      = (const float*)d_in[10];
    const float* w_bih      = (const float*)d_in[11];
    const float* w_bhh      = (const float*)d_in[12];
    const float* cls_W      = (const float*)d_in[13];
    const float* cls_b      = (const float*)d_in[14];
    float* out = (float*)d_out;

    float *pA, *pWc, *pbc, *pgates, *pbw, *pF, *pwg, *ph;
    cudaGetSymbolAddress((void**)&pA,     g_A);
    cudaGetSymbolAddress((void**)&pWc,    g_Wc);
    cudaGetSymbolAddress((void**)&pbc,    g_bc);
    cudaGetSymbolAddress((void**)&pgates, g_gates);
    cudaGetSymbolAddress((void**)&pbw,    g_bw);
    cudaGetSymbolAddress((void**)&pF,     g_F);
    cudaGetSymbolAddress((void**)&pwg,    g_wg);
    cudaGetSymbolAddress((void**)&ph,     g_h);

    prep_kernel<<<1024, 256>>>(chars, char_embed, c_Wih, c_Whh,
                               c_bih, c_bhh, w_bih, w_bhh);

    // char LSTM: 16 x (gates GEMM + pointwise)
    for (int t = 0; t < L_CHARS; t++) {
        gemm_bias<<<dim3(S_LEN / 128, 512 / 64), 256>>>(
            pA, pWc, pbc, pgates, CK, 512, 0);
        char_pointwise<<<(S_LEN * CHAR_HID) / 256, 256>>>(
            chars, char_lens, char_embed, t);
    }

    // word features + input-gate precompute (unit-blocked, biases folded)
    feats_kernel<<<(S_LEN * WK + 255) / 256, 256>>>(x, word_embed);
    gemm_bias<<<dim3(S_LEN / 128, 2048 / 64), 256>>>(
        pF, w_Wih, pbw, pwg, WK, 2048, 1);

    // sequential word LSTM (persistent, hierarchical flag wait)
    word_lstm_kernel<<<GW2, TPB2>>>(w_Whh);

    // classifier: out = h_all @ cls_W^T + cls_b  (A offset by one row: h[1..S])
    gemm_bias<<<dim3(S_LEN / 128, 1), 256>>>(
        ph + 512, cls_W, cls_b, out, 512, N_TAG, 0);
}